// round 17
// baseline (speedup 1.0000x reference)
#include <cuda_runtime.h>
#include <cuda_fp16.h>
#include <mma.h>
#include <cstdint>

#define BB 4
#define SS 1024
#define DD 1024
#define HH 16
#define HD 64
#define KK 1024

// Scratch (__device__ globals — allocation-free rule)
static __device__ __half g_qh[BB * HH * SS * HD];   // fp16 q, pre-scaled
static __device__ __half g_kh[BB * HH * SS * HD];   // fp16 k
static __device__ __half g_vth[BB * HH * HD * SS];  // fp16 v TRANSPOSED [bh][hd][S]
static __device__ __half g_xh[BB * SS * DD];        // fp16 x [M][K]
static __device__ __half g_wqkvh[3 * DD * DD];      // fp16 Wqkv^T [N][K]
static __device__ __half g_woh[DD * DD];            // fp16 Wo^T   [N][K]
static __device__ __half g_aoh[BB * SS * DD];       // fp16 attn out [M][K]
static __device__ uint32_t g_mb[BB * SS * (SS / 32)];

__device__ __forceinline__ void cpa16(void* dst, const void* src) {
    unsigned d = (unsigned)__cvta_generic_to_shared(dst);
    asm volatile("cp.async.cg.shared.global [%0], [%1], 16;\n" :: "r"(d), "l"(src));
}
#define CP_COMMIT() asm volatile("cp.async.commit_group;\n" ::)
#define CP_WAIT(N)  asm volatile("cp.async.wait_group %0;\n" :: "n"(N))

// fp16 m16n8k16 mma (A row-major, B col-major), fp32 accum, in place
__device__ __forceinline__ void mma16(float* d, const uint32_t* a,
                                      uint32_t b0, uint32_t b1) {
    asm volatile(
        "mma.sync.aligned.m16n8k16.row.col.f32.f16.f16.f32 "
        "{%0,%1,%2,%3}, {%4,%5,%6,%7}, {%8,%9}, {%0,%1,%2,%3};"
        : "+f"(d[0]), "+f"(d[1]), "+f"(d[2]), "+f"(d[3])
        : "r"(a[0]), "r"(a[1]), "r"(a[2]), "r"(a[3]), "r"(b0), "r"(b1));
}

// ldmatrix x4 (non-transposed)
__device__ __forceinline__ void ldsm4(uint32_t* r, uint32_t addr) {
    asm volatile(
        "ldmatrix.sync.aligned.m8n8.x4.shared.b16 {%0,%1,%2,%3}, [%4];"
        : "=r"(r[0]), "=r"(r[1]), "=r"(r[2]), "=r"(r[3]) : "r"(addr));
}

// ---------------------------------------------------------------------------
// Single fused pre-pass (one launch): weight transposes + x->fp16 + mask pack
// ---------------------------------------------------------------------------
#define N4_X  (BB * SS * DD / 4)
#define N_MW  (BB * SS * (SS / 32))
#define TQ_TILES ((3 * DD / 32) * (KK / 32))
#define TO_TILES ((DD / 32) * (KK / 32))
#define LIN_BLOCKS ((N4_X + N_MW + 255) / 256)
#define PRE_BLOCKS (TQ_TILES + TO_TILES + LIN_BLOCKS)

__global__ void __launch_bounds__(256) prepass_k(
    const float4* __restrict__ x4, const float* __restrict__ Wqkv,
    const float* __restrict__ Wo, const int* __restrict__ mask)
{
    __shared__ float tbuf[32][33];
    const int bid = blockIdx.x;
    const int tid = threadIdx.x;

    if (bid < TQ_TILES + TO_TILES) {
        const bool isQ = bid < TQ_TILES;
        const int t = isQ ? bid : bid - TQ_TILES;
        const int C = isQ ? 3 * DD : DD;
        const float* src = isQ ? Wqkv : Wo;
        __half* dst = isQ ? g_wqkvh : g_woh;
        const int bx = (t % (C / 32)) * 32;
        const int by = (t / (C / 32)) * 32;
        const int tx = tid & 31, ty = tid >> 5;
#pragma unroll
        for (int i = 0; i < 4; i++)
            tbuf[ty + i * 8][tx] =
                src[(size_t)(by + ty + i * 8) * C + bx + tx];
        __syncthreads();
#pragma unroll
        for (int i = 0; i < 4; i++)
            dst[(size_t)(bx + ty + i * 8) * KK + by + tx] =
                __float2half_rn(tbuf[tx][ty + i * 8]);
    } else {
        const int i = (bid - TQ_TILES - TO_TILES) * 256 + tid;
        if (i < N4_X) {
            float4 v = x4[i];
            __half2* dst = (__half2*)g_xh + i * 2;
            dst[0] = __floats2half2_rn(v.x, v.y);
            dst[1] = __floats2half2_rn(v.z, v.w);
        } else if (i < N4_X + N_MW) {
            int m = i - N4_X;
            const int4* src = (const int4*)(mask + (size_t)m * 32);
            uint32_t w = 0;
#pragma unroll
            for (int k = 0; k < 8; k++) {
                int4 v = src[k];
                w |= (v.x != 0 ? 1u : 0u) << (k * 4 + 0);
                w |= (v.y != 0 ? 1u : 0u) << (k * 4 + 1);
                w |= (v.z != 0 ? 1u : 0u) << (k * 4 + 2);
                w |= (v.w != 0 ? 1u : 0u) << (k * 4 + 3);
            }
            g_mb[m] = w;
        }
    }
}

// ---------------------------------------------------------------------------
// fp16 mma.sync GEMM (round-16, unchanged). 256 thr, warp tile 64x32,
// CTA 128x128, BK=64, 3-stage cp.async ring, ldmatrix frags.
// ---------------------------------------------------------------------------
#define HSTG 18432
#define GSMEM (3 * HSTG * 2)

template <int MODE>
__global__ void __launch_bounds__(256, 2) hgemm_k(
    const float* __restrict__ bias, float* __restrict__ C, int N)
{
    extern __shared__ __half hsm[];

    const int tid = threadIdx.x, lane = tid & 31, warp = tid >> 5;
    const int g = lane >> 2, tig = lane & 3;
    const int wm = (warp >> 2) * 64, wn = (warp & 3) * 32;
    const int m0 = blockIdx.y * 128, n0 = blockIdx.x * 128;

    const __half* Ap = (MODE == 0) ? (const __half*)g_xh : (const __half*)g_aoh;
    const __half* Bp = (MODE == 0) ? (const __half*)g_wqkvh : (const __half*)g_woh;

    const uint32_t smem0 = (uint32_t)__cvta_generic_to_shared(hsm);
    const int aoff = (wm + (lane & 15)) * 72 + (lane >> 4) * 8;
    const int boff = (wn + ((lane >> 4) & 1) * 8 + (lane & 7)) * 72 +
                     ((lane >> 3) & 1) * 8;

    auto issue = [&](int st, int k0) {
        __half* As = hsm + st * HSTG;
        __half* Bs = As + 9216;
#pragma unroll
        for (int v = 0; v < 4; v++) {
            int id = tid + v * 256;
            int row = id >> 3, c = id & 7;
            cpa16(&As[row * 72 + c * 8],
                  Ap + (size_t)(m0 + row) * KK + k0 + c * 8);
            cpa16(&Bs[row * 72 + c * 8],
                  Bp + (size_t)(n0 + row) * KK + k0 + c * 8);
        }
    };

    float d[4][4][4];
#pragma unroll
    for (int mf = 0; mf < 4; mf++)
#pragma unroll
        for (int nf = 0; nf < 4; nf++)
#pragma unroll
            for (int c = 0; c < 4; c++) d[mf][nf][c] = 0.0f;

    issue(0, 0);  CP_COMMIT();
    issue(1, 64); CP_COMMIT();

    const int NI = KK / 64;
    for (int i = 0; i < NI; i++) {
        const int st = i % 3;
        CP_WAIT(1);
        __syncthreads();
        if (i + 2 < NI) issue((i + 2) % 3, (i + 2) * 64);
        CP_COMMIT();

        const uint32_t Ab = smem0 + (st * HSTG) * 2;
        const uint32_t Aaddr = Ab + aoff * 2;
        const uint32_t Baddr = Ab + 9216 * 2 + boff * 2;

#pragma unroll
        for (int kk = 0; kk < 4; kk++) {
            uint32_t af[4][4], bf[2][4];
#pragma unroll
            for (int mf = 0; mf < 4; mf++)
                ldsm4(af[mf], Aaddr + (mf * 16 * 72 + kk * 16) * 2);
#pragma unroll
            for (int nfp = 0; nfp < 2; nfp++)
                ldsm4(bf[nfp], Baddr + (nfp * 16 * 72 + kk * 16) * 2);
#pragma unroll
            for (int mf = 0; mf < 4; mf++)
#pragma unroll
                for (int nfp = 0; nfp < 2; nfp++) {
                    mma16(d[mf][nfp * 2],     af[mf], bf[nfp][0], bf[nfp][1]);
                    mma16(d[mf][nfp * 2 + 1], af[mf], bf[nfp][2], bf[nfp][3]);
                }
        }
    }

    // ---- epilogue ----
#pragma unroll
    for (int mf = 0; mf < 4; mf++) {
        const int m = m0 + wm + mf * 16 + g;
        const int bb = m >> 10, srow = m & 1023;
#pragma unroll
        for (int nf = 0; nf < 4; nf++) {
            const int col0 = n0 + wn + nf * 8 + 2 * tig;
            const float b0 = bias[col0], b1 = bias[col0 + 1];
            float v0 = d[mf][nf][0] + b0, v1 = d[mf][nf][1] + b1;
            float v2 = d[mf][nf][2] + b0, v3 = d[mf][nf][3] + b1;

            if (MODE == 0) {
                const int h = col0 / 192;
                const int rr = col0 - h * 192;
                const int seg = rr >> 6;
                const int db = rr & 63;
                const size_t bhb = (size_t)(bb * HH + h);
                if (seg == 2) {
                    __half* vd = g_vth + (bhb * HD + db) * SS;
                    vd[srow]          = __float2half_rn(v0);
                    vd[SS + srow]     = __float2half_rn(v1);
                    vd[srow + 8]      = __float2half_rn(v2);
                    vd[SS + srow + 8] = __float2half_rn(v3);
                } else {
                    __half* dst = (seg == 0) ? g_qh : g_kh;
                    const float sc = (seg == 0) ? 0.125f : 1.0f;
                    const size_t idx = (bhb * SS + srow) * HD + db;
                    *(__half2*)&dst[idx] =
                        __floats2half2_rn(v0 * sc, v1 * sc);
                    *(__half2*)&dst[idx + 8 * HD] =
                        __floats2half2_rn(v2 * sc, v3 * sc);
                }
            } else {
                float* dst = C + (size_t)m * N + col0;
                *(float2*)dst           = make_float2(v0, v1);
                *(float2*)(dst + 8 * N) = make_float2(v2, v3);
            }
        }
    }
}

// ---------------------------------------------------------------------------
// Flash attention FA2, fp16 mma + ldmatrix. 256 thr (8 warps), q-block 128,
// warp q-tile 16 (ONE m-frag) — 4 warps/SMSP so softmax overlaps mma.
// smem halves: Qs[128][72] | Ks[2][64][72] | Vt[2][64][72]. 55296 B.
// ---------------------------------------------------------------------------
#define LDH 72
#define NT (SS / 64)
#define ATTN_SMEM (27648 * 2)

__global__ void __launch_bounds__(256, 2) attn_k(void)
{
    extern __shared__ __half hsm[];
    __half* Qs = hsm;
    __half* Ks = hsm + 9216;
    __half* Vs = hsm + 18432;

    const int tid = threadIdx.x, lane = tid & 31, warp = tid >> 5;
    const int g = lane >> 2, tig = lane & 3;
    const int q0 = blockIdx.x * 128;
    const int h = blockIdx.y, b = blockIdx.z;
    const size_t bh = (size_t)(b * HH + h);
    const __half* qb  = g_qh  + bh * SS * HD;
    const __half* kb  = g_kh  + bh * SS * HD;
    const __half* vtb = g_vth + bh * HD * SS;

    const uint32_t smem0 = (uint32_t)__cvta_generic_to_shared(hsm);
    const uint32_t Qb = smem0;
    const int rb = 16 * warp;          // 16 q rows per warp
    const int aoff = (rb + (lane & 15)) * LDH + (lane >> 4) * 8;
    const int boff = (((lane >> 4) & 1) * 8 + (lane & 7)) * LDH +
                     ((lane >> 3) & 1) * 8;

#pragma unroll
    for (int j = 0; j < 4; j++) {
        int idx = tid + j * 256;
        int r = idx >> 3, c = idx & 7;
        cpa16(&Qs[r * LDH + c * 8], qb + (size_t)(q0 + r) * HD + c * 8);
    }
#pragma unroll
    for (int j = 0; j < 2; j++) {
        int idx = tid + j * 256;
        int r = idx >> 3, c = idx & 7;
        cpa16(&Ks[r * LDH + c * 8], kb + (size_t)r * HD + c * 8);
        cpa16(&Vs[r * LDH + c * 8], vtb + (size_t)r * SS + c * 8);
    }
    CP_COMMIT();
    CP_WAIT(0);
    __syncthreads();

    // Q A-frags (one m-frag, 4 k-steps)
    uint32_t qf[4][4];
#pragma unroll
    for (int kk = 0; kk < 4; kk++)
        ldsm4(qf[kk], Qb + (aoff + kk * 16) * 2);
    __syncthreads();   // Qs is now the P buffer

    float o[8][4];
#pragma unroll
    for (int j = 0; j < 8; j++)
#pragma unroll
        for (int c = 0; c < 4; c++) o[j][c] = 0.0f;
    float mi0 = -1e30f, mi1 = -1e30f, li0 = 0.0f, li1 = 0.0f;

    const int r0 = rb + g, r1 = rb + g + 8;
    const uint32_t* mb0 = g_mb + ((size_t)b * SS + (q0 + r0)) * 32;
    const uint32_t* mb1 = g_mb + ((size_t)b * SS + (q0 + r1)) * 32;

    for (int t = 0; t < NT; t++) {
        const int st = t & 1;
        if (t + 1 < NT) {
            const __half* kb2  = kb  + (size_t)(t + 1) * 64 * HD;
            const __half* vtb2 = vtb + (size_t)(t + 1) * 64;
            __half* Kd = Ks + (st ^ 1) * 4608;
            __half* Vd = Vs + (st ^ 1) * 4608;
#pragma unroll
            for (int j = 0; j < 2; j++) {
                int idx = tid + j * 256;
                int r = idx >> 3, c = idx & 7;
                cpa16(&Kd[r * LDH + c * 8], kb2 + (size_t)r * HD + c * 8);
                cpa16(&Vd[r * LDH + c * 8], vtb2 + (size_t)r * SS + c * 8);
            }
        }
        CP_COMMIT();

        uint2 mw0 = *(const uint2*)(mb0 + t * 2);
        uint2 mw1 = *(const uint2*)(mb1 + t * 2);

        CP_WAIT(1);
        __syncthreads();

        const uint32_t Kbase = smem0 + (9216 + st * 4608) * 2;
        const uint32_t Vbase = smem0 + (18432 + st * 4608) * 2;

        // ---- S = Q @ K^T ----
        float s[8][4];
#pragma unroll
        for (int jp = 0; jp < 4; jp++) {
            const int j0 = jp * 2, j1 = j0 + 1;
            s[j0][0] = s[j0][1] = s[j0][2] = s[j0][3] = 0.0f;
            s[j1][0] = s[j1][1] = s[j1][2] = s[j1][3] = 0.0f;
#pragma unroll
            for (int kk = 0; kk < 4; kk++) {
                uint32_t kf[4];
                ldsm4(kf, Kbase + (boff + jp * 16 * LDH + kk * 16) * 2);
                mma16(s[j0], qf[kk], kf[0], kf[1]);
                mma16(s[j1], qf[kk], kf[2], kf[3]);
            }
        }

        // ---- bitmask ----
#pragma unroll
        for (int j = 0; j < 8; j++) {
            const int bit = (j * 8 + 2 * tig) & 31;
            const uint32_t wa = (j < 4) ? mw0.x : mw0.y;
            const uint32_t wb = (j < 4) ? mw1.x : mw1.y;
            if (!((wa >> bit) & 1))       s[j][0] = -1e20f;
            if (!((wa >> (bit + 1)) & 1)) s[j][1] = -1e20f;
            if (!((wb >> bit) & 1))       s[j][2] = -1e20f;
            if (!((wb >> (bit + 1)) & 1)) s[j][3] = -1e20f;
        }

        // ---- online softmax; stage fp16 P into Qs ----
        {
            float mx0 = s[0][0], mx1 = s[0][2];
#pragma unroll
            for (int j = 0; j < 8; j++) {
                mx0 = fmaxf(mx0, fmaxf(s[j][0], s[j][1]));
                mx1 = fmaxf(mx1, fmaxf(s[j][2], s[j][3]));
            }
            mx0 = fmaxf(mx0, __shfl_xor_sync(0xffffffffu, mx0, 1));
            mx0 = fmaxf(mx0, __shfl_xor_sync(0xffffffffu, mx0, 2));
            mx1 = fmaxf(mx1, __shfl_xor_sync(0xffffffffu, mx1, 1));
            mx1 = fmaxf(mx1, __shfl_xor_sync(0xffffffffu, mx1, 2));
            const float mn0 = fmaxf(mi0, mx0);
            const float mn1 = fmaxf(mi1, mx1);
            const float a0 = __expf(mi0 - mn0);
            const float a1 = __expf(mi1 - mn1);
            float rs0 = 0.0f, rs1 = 0.0f;
#pragma unroll
            for (int j = 0; j < 8; j++) {
                s[j][0] = __expf(s[j][0] - mn0);
                s[j][1] = __expf(s[j][1] - mn0);
                s[j][2] = __expf(s[j][2] - mn1);
                s[j][3] = __expf(s[j][3] - mn1);
                rs0 += s[j][0] + s[j][1];
                rs1 += s[j][2] + s[j][3];
                *(__half2*)&Qs[r0 * LDH + j * 8 + 2 * tig] =
                    __floats2half2_rn(s[j][0], s[j][1]);
                *(__half2*)&Qs[r1 * LDH + j * 8 + 2 * tig] =
                    __floats2half2_rn(s[j][2], s[j][3]);
            }
            rs0 += __shfl_xor_sync(0xffffffffu, rs0, 1);
            rs0 += __shfl_xor_sync(0xffffffffu, rs0, 2);
            rs1 += __shfl_xor_sync(0xffffffffu, rs1, 1);
            rs1 += __shfl_xor_sync(0xffffffffu, rs1, 2);
            li0 = li0 * a0 + rs0;
            li1 = li1 * a1 + rs1;
            mi0 = mn0; mi1 = mn1;
#pragma unroll
            for (int j = 0; j < 8; j++) {
                o[j][0] *= a0; o[j][1] *= a0;
                o[j][2] *= a1; o[j][3] *= a1;
            }
        }
        __syncwarp();

        // ---- O += P @ V ----
#pragma unroll
        for (int kk = 0; kk < 4; kk++) {
            uint32_t pa[4];
            ldsm4(pa, Qb + (aoff + kk * 16) * 2);
#pragma unroll
            for (int jp = 0; jp < 4; jp++) {
                uint32_t vf[4];
                ldsm4(vf, Vbase + (boff + jp * 16 * LDH + kk * 16) * 2);
                mma16(o[jp * 2],     pa, vf[0], vf[1]);
                mma16(o[jp * 2 + 1], pa, vf[2], vf[3]);
            }
        }
        __syncthreads();
    }

    // ---- normalize + write fp16 g_aoh ----
    {
        const float inv0 = 1.0f / li0, inv1 = 1.0f / li1;
        __half* dst0 = g_aoh + ((size_t)b * SS + (q0 + r0)) * DD + h * HD;
        __half* dst1 = g_aoh + ((size_t)b * SS + (q0 + r1)) * DD + h * HD;
#pragma unroll
        for (int j = 0; j < 8; j++) {
            *(__half2*)&dst0[j * 8 + 2 * tig] =
                __floats2half2_rn(o[j][0] * inv0, o[j][1] * inv0);
            *(__half2*)&dst1[j * 8 + 2 * tig] =
                __floats2half2_rn(o[j][2] * inv1, o[j][3] * inv1);
        }
    }
}

// ---------------------------------------------------------------------------
extern "C" void kernel_launch(void* const* d_in, const int* in_sizes, int n_in,
                              void* d_out, int out_size)
{
    const float* x    = (const float*)d_in[0];
    const int*   mask = (const int*)  d_in[1];
    const float* Wqkv = (const float*)d_in[2];
    const float* bqkv = (const float*)d_in[3];
    const float* Wo   = (const float*)d_in[4];
    const float* bo   = (const float*)d_in[5];
    float* out = (float*)d_out;
    (void)in_sizes; (void)n_in; (void)out_size;

    cudaFuncSetAttribute(attn_k, cudaFuncAttributeMaxDynamicSharedMemorySize,
                         ATTN_SMEM);
    cudaFuncSetAttribute(hgemm_k<0>, cudaFuncAttributeMaxDynamicSharedMemorySize,
                         GSMEM);
    cudaFuncSetAttribute(hgemm_k<1>, cudaFuncAttributeMaxDynamicSharedMemorySize,
                         GSMEM);

    // 0) single fused pre-pass
    prepass_k<<<PRE_BLOCKS, 256>>>((const float4*)x, Wqkv, Wo, mask);

    // 1) QKV projection -> fp16 q/k + transposed v
    {
        dim3 grid(3 * DD / 128, (BB * SS) / 128);
        hgemm_k<0><<<grid, 256, GSMEM>>>(bqkv, nullptr, 3 * DD);
    }

    // 2) Flash attention (256 thr) -> g_aoh (fp16)
    attn_k<<<dim3(SS / 128, HH, BB), 256, ATTN_SMEM>>>();

    // 3) Output projection -> d_out (fp32)
    {
        dim3 grid(DD / 128, (BB * SS) / 128);
        hgemm_k<1><<<grid, 256, GSMEM>>>(bo, out, DD);
    }
}